// round 6
// baseline (speedup 1.0000x reference)
#include <cuda_runtime.h>
#include <cuda_bf16.h>

#define BQ 2048
#define NS 32768
#define DD 256
#define NC 100

#define MT 128
#define NT 128
#define KT 32
#define NSPLIT 9
#define NTILES (NS / NT)   // 256

// Scratch (no device allocation allowed)
__device__ float g_s2[NS];
__device__ float g_pval[BQ * NSPLIT];
__device__ int   g_pidx[BQ * NSPLIT];
__device__ int   g_lab64;

// ---------------------------------------------------------------------------
// Detect whether support_labels is int64 (odd 32-bit words all zero) or int32
// ---------------------------------------------------------------------------
__global__ void detect_labels_kernel(const int* __restrict__ labs) {
    if (threadIdx.x == 0) {
        int f = 1;
        for (int i = 0; i < 128; i++) {
            if (labs[2 * i + 1] != 0) { f = 0; break; }
        }
        g_lab64 = f;
    }
}

// ---------------------------------------------------------------------------
// ||s_n||^2 for all support rows. blockDim = (32, 8): one warp per row.
// ---------------------------------------------------------------------------
__global__ void s2_kernel(const float* __restrict__ S) {
    int row = blockIdx.x * 8 + threadIdx.y;
    const float4* p = (const float4*)(S + (size_t)row * DD);
    float s = 0.0f;
    #pragma unroll
    for (int i = threadIdx.x; i < DD / 4; i += 32) {
        float4 v = p[i];
        s += v.x * v.x + v.y * v.y + v.z * v.z + v.w * v.w;
    }
    #pragma unroll
    for (int o = 16; o; o >>= 1) s += __shfl_xor_sync(0xffffffffu, s, o);
    if (threadIdx.x == 0) g_s2[row] = s;
}

// ---------------------------------------------------------------------------
// Fused GEMM + argmin. grid = (BQ/MT, NSPLIT), block = 256 threads.
// Thread (ty,tx) computes an 8x8 microtile; keeps running (val,idx) best
// per row across its support tiles. Tie-break: lowest global index.
// ---------------------------------------------------------------------------
__global__ void __launch_bounds__(256, 1)
knn_kernel(const float* __restrict__ X, const float* __restrict__ S) {
    __shared__ __align__(16) float As[KT][MT + 4];
    __shared__ __align__(16) float Bs[KT][NT + 4];
    __shared__ float s2s[NT];

    const int tid = threadIdx.x;
    const int tx = tid & 15;        // 0..15  -> 8 support cols
    const int ty = tid >> 4;        // 0..15  -> 8 query rows
    const int brow0 = blockIdx.x * MT;

    float bestv[8];
    int   bestidx[8];
    #pragma unroll
    for (int i = 0; i < 8; i++) { bestv[i] = 3.4e38f; bestidx[i] = 0; }

    for (int st = blockIdx.y; st < NTILES; st += NSPLIT) {
        const int col0 = st * NT;

        __syncthreads();                       // prior epilogue done before s2s rewrite
        if (tid < NT) s2s[tid] = g_s2[col0 + tid];

        float acc[8][8];
        #pragma unroll
        for (int i = 0; i < 8; i++)
            #pragma unroll
            for (int j = 0; j < 8; j++) acc[i][j] = 0.0f;

        for (int kt = 0; kt < DD; kt += KT) {
            __syncthreads();
            // Load A tile (128 x 32) and B tile (128 x 32), k-major in smem.
            #pragma unroll
            for (int i = 0; i < 4; i++) {
                int idx = tid + i * 256;       // 0..1023
                int r  = idx >> 3;             // row within tile 0..127
                int kq = (idx & 7) * 4;        // k-quad 0,4,...,28
                float4 va = *(const float4*)&X[(size_t)(brow0 + r) * DD + kt + kq];
                As[kq + 0][r] = va.x; As[kq + 1][r] = va.y;
                As[kq + 2][r] = va.z; As[kq + 3][r] = va.w;
                float4 vb = *(const float4*)&S[(size_t)(col0 + r) * DD + kt + kq];
                Bs[kq + 0][r] = vb.x; Bs[kq + 1][r] = vb.y;
                Bs[kq + 2][r] = vb.z; Bs[kq + 3][r] = vb.w;
            }
            __syncthreads();

            #pragma unroll
            for (int k = 0; k < KT; k++) {
                float a[8], b[8];
                *(float4*)&a[0] = *(const float4*)&As[k][ty * 8];
                *(float4*)&a[4] = *(const float4*)&As[k][ty * 8 + 4];
                *(float4*)&b[0] = *(const float4*)&Bs[k][tx * 8];
                *(float4*)&b[4] = *(const float4*)&Bs[k][tx * 8 + 4];
                #pragma unroll
                for (int i = 0; i < 8; i++)
                    #pragma unroll
                    for (int j = 0; j < 8; j++)
                        acc[i][j] += a[i] * b[j];
            }
        }

        // Epilogue: score = ||s||^2 - 2*dot ; running lexicographic min.
        #pragma unroll
        for (int i = 0; i < 8; i++) {
            #pragma unroll
            for (int j = 0; j < 8; j++) {
                int c = tx * 8 + j;
                float sc = s2s[c] - 2.0f * acc[i][j];
                int gidx = col0 + c;
                if (sc < bestv[i] || (sc == bestv[i] && gidx < bestidx[i])) {
                    bestv[i] = sc;
                    bestidx[i] = gidx;
                }
            }
        }
    }

    // Cross-thread reduction over the 16 tx lanes sharing each query row.
    __syncthreads();
    float* redv = &As[0][0];            // 128*16 floats fits in As
    int*   redi = (int*)&Bs[0][0];      // 128*16 ints fits in Bs
    #pragma unroll
    for (int i = 0; i < 8; i++) {
        int r = ty * 8 + i;
        redv[r * 16 + tx] = bestv[i];
        redi[r * 16 + tx] = bestidx[i];
    }
    __syncthreads();
    if (tid < MT) {
        float bv = redv[tid * 16];
        int   bi = redi[tid * 16];
        #pragma unroll
        for (int t = 1; t < 16; t++) {
            float v = redv[tid * 16 + t];
            int  ix = redi[tid * 16 + t];
            if (v < bv || (v == bv && ix < bi)) { bv = v; bi = ix; }
        }
        g_pval[(size_t)(brow0 + tid) * NSPLIT + blockIdx.y] = bv;
        g_pidx[(size_t)(brow0 + tid) * NSPLIT + blockIdx.y] = bi;
    }
}

// ---------------------------------------------------------------------------
// Final: reduce NSPLIT partials per query, gather label, emit one-hot as
// FLOAT32 (harness output dtype). grid = BQ blocks x 32 threads.
// ---------------------------------------------------------------------------
__global__ void final_kernel(const void* __restrict__ labs, float* __restrict__ out) {
    int b = blockIdx.x;
    int lane = threadIdx.x;
    float bv = 3.4e38f;
    int   bi = NS + 1;                  // sentinel loses all index ties
    if (lane < NSPLIT) {
        bv = g_pval[(size_t)b * NSPLIT + lane];
        bi = g_pidx[(size_t)b * NSPLIT + lane];
    }
    #pragma unroll
    for (int o = 16; o; o >>= 1) {
        float ov = __shfl_xor_sync(0xffffffffu, bv, o);
        int   oi = __shfl_xor_sync(0xffffffffu, bi, o);
        if (ov < bv || (ov == bv && oi < bi)) { bv = ov; bi = oi; }
    }
    // Safety clamp: never OOB-gather even if something upstream went wrong.
    bi = min(max(bi, 0), NS - 1);
    int label;
    if (g_lab64) label = (int)((const long long*)labs)[bi];
    else         label = ((const int*)labs)[bi];

    for (int c = lane; c < NC; c += 32)
        out[(size_t)b * NC + c] = (c == label) ? 1.0f : 0.0f;
}

extern "C" void kernel_launch(void* const* d_in, const int* in_sizes, int n_in,
                              void* d_out, int out_size) {
    // Identify inputs by element count — robust to any metadata ordering.
    //   x: 2048*256 = 524288 f32 | S: 32768*256 = 8388608 f32
    //   labels: 32768 (int32 or int64) | num_classes: 1 (unused)
    const float* X = 0;
    const float* S = 0;
    const void*  L = 0;
    for (int i = 0; i < n_in; i++) {
        if (in_sizes[i] == BQ * DD)      X = (const float*)d_in[i];
        else if (in_sizes[i] == NS * DD) S = (const float*)d_in[i];
        else if (in_sizes[i] == NS)      L = d_in[i];
    }
    float* out = (float*)d_out;                       // [2048, 100] float32

    detect_labels_kernel<<<1, 32>>>((const int*)L);
    s2_kernel<<<NS / 8, dim3(32, 8)>>>(S);
    dim3 grid(BQ / MT, NSPLIT);
    knn_kernel<<<grid, 256>>>(X, S);
    final_kernel<<<BQ, 32>>>(L, out);
}

// round 8
// speedup vs baseline: 1.8606x; 1.8606x over previous
#include <cuda_runtime.h>
#include <cuda_bf16.h>
#include <cstdint>

#define BQ 2048
#define NS 32768
#define DD 256
#define NC 100

#define KP 768              // packed K: X'=[hi,hi,lo], S'=[hi,lo,hi]
#define MT 128              // CTA M tile
#define NT 128              // CTA N tile
#define KT 32               // bf16 per K chunk
#define NCH (KP / KT)       // 24 chunks
#define NSPLIT 9
#define NTILES (NS / NT)    // 256

// ---------------- device globals (no runtime allocation allowed) -----------
__device__ __nv_bfloat16 g_Xp[(size_t)BQ * KP];   // 3 MB
__device__ __nv_bfloat16 g_Sp[(size_t)NS * KP];   // 48 MB
__device__ float g_s2[NS];
__device__ float g_pval[BQ * NSPLIT];
__device__ int   g_pidx[BQ * NSPLIT];
__device__ int   g_lab64;

// ---------------- helpers ---------------------------------------------------
__device__ __forceinline__ uint32_t smem_u32(const void* p) {
    uint32_t a;
    asm("{ .reg .u64 t; cvta.to.shared.u64 t, %1; cvt.u32.u64 %0, t; }"
        : "=r"(a) : "l"(p));
    return a;
}
__device__ __forceinline__ uint32_t sw(uint32_t byte_off) {
    // rows are 64B; spread 8 consecutive rows across the 8 16B chunks of 128B
    return byte_off ^ ((byte_off >> 3) & 0x30);   // XOR bits[5:4] with bits[8:7]... see note
}
// NOTE on sw(): byte = r*64 + q*16. (byte>>3)&0x30 = ((r*8+2q)&0x30) = (r&6)<<3.
// chunk-in-128B = (4r + ((r&6)>>1)*? ) -> rows 0..7 map to chunks {0,4,1,5,2,6,3,7}: conflict-free.

#define CP_ASYNC16(dst, src) \
    asm volatile("cp.async.cg.shared.global [%0], [%1], 16;" :: "r"(dst), "l"(src) : "memory")
#define CP_COMMIT() asm volatile("cp.async.commit_group;" ::: "memory")
#define CP_WAIT1()  asm volatile("cp.async.wait_group 1;" ::: "memory")
#define CP_WAIT0()  asm volatile("cp.async.wait_group 0;" ::: "memory")

#define LDSM_X4(r0, r1, r2, r3, addr) \
    asm volatile("ldmatrix.sync.aligned.m8n8.x4.shared.b16 {%0,%1,%2,%3}, [%4];" \
                 : "=r"(r0), "=r"(r1), "=r"(r2), "=r"(r3) : "r"(addr))

#define MMA16816(c0, c1, c2, c3, a0, a1, a2, a3, b0, b1) \
    asm volatile("mma.sync.aligned.m16n8k16.row.col.f32.bf16.bf16.f32 " \
                 "{%0,%1,%2,%3}, {%4,%5,%6,%7}, {%8,%9}, {%0,%1,%2,%3};" \
                 : "+f"(c0), "+f"(c1), "+f"(c2), "+f"(c3) \
                 : "r"(a0), "r"(a1), "r"(a2), "r"(a3), "r"(b0), "r"(b1))

// ---------------- small kernels ---------------------------------------------
__global__ void detect_labels_kernel(const int* __restrict__ labs) {
    if (threadIdx.x == 0) {
        int f = 1;
        for (int i = 0; i < 128; i++)
            if (labs[2 * i + 1] != 0) { f = 0; break; }
        g_lab64 = f;
    }
}

__global__ void s2_kernel(const float* __restrict__ S) {
    int row = blockIdx.x * 8 + threadIdx.y;
    const float4* p = (const float4*)(S + (size_t)row * DD);
    float s = 0.0f;
    #pragma unroll
    for (int i = threadIdx.x; i < DD / 4; i += 32) {
        float4 v = p[i];
        s += v.x * v.x + v.y * v.y + v.z * v.z + v.w * v.w;
    }
    #pragma unroll
    for (int o = 16; o; o >>= 1) s += __shfl_xor_sync(0xffffffffu, s, o);
    if (threadIdx.x == 0) g_s2[row] = s;
}

// f32 -> (hi, lo) bf16 split; X' = [hi, hi, lo], S' = [hi, lo, hi]
__global__ void pack_kernel(const float* __restrict__ src, int rows, int isS) {
    int idx = blockIdx.x * 256 + threadIdx.x;
    if (idx >= rows * DD) return;
    int r = idx >> 8, k = idx & 255;
    float v = src[idx];
    __nv_bfloat16 hi = __float2bfloat16(v);
    __nv_bfloat16 lo = __float2bfloat16(v - __bfloat162float(hi));
    size_t base = (size_t)r * KP;
    if (isS) { g_Sp[base + k] = hi; g_Sp[base + 256 + k] = lo; g_Sp[base + 512 + k] = hi; }
    else     { g_Xp[base + k] = hi; g_Xp[base + 256 + k] = hi; g_Xp[base + 512 + k] = lo; }
}

// ---------------- main mma.sync kernel --------------------------------------
// grid (BQ/MT, NSPLIT) = (16, 9), block 256 (8 warps: 4 m x 2 n, 32x64 each)
__global__ void __launch_bounds__(256)
knn_mma_kernel() {
    __shared__ __align__(128) char As[2][MT * KT * 2];   // 8 KB each
    __shared__ __align__(128) char Bs[2][NT * KT * 2];   // 8 KB each
    __shared__ float s2s[NT];
    __shared__ float redv[2][MT];
    __shared__ int   redi[2][MT];

    const int tid  = threadIdx.x;
    const int lane = tid & 31;
    const int wid  = tid >> 5;
    const int wm   = wid & 3;          // warp m: 0..3  (32 rows each)
    const int wn   = wid >> 2;         // warp n: 0..1  (64 cols each)
    const int brow0 = blockIdx.x * MT;
    const int grp   = blockIdx.y;

    const uint32_t sbA[2] = { smem_u32(As[0]), smem_u32(As[1]) };
    const uint32_t sbB[2] = { smem_u32(Bs[0]), smem_u32(Bs[1]) };

    float bestv[4];
    int   besti[4];
    #pragma unroll
    for (int b = 0; b < 4; b++) { bestv[b] = 3.4e38f; besti[b] = 0; }

    // ldmatrix row/col-within-tile for this lane (same pattern for A and B)
    const int lrow = lane & 15;          // row within 16-row block
    const int lkof = (lane >> 4) * 8;    // k offset 0 or 8

    for (int st = grp; st < NTILES; st += NSPLIT) {
        const int col0 = st * NT;
        if (tid < NT) s2s[tid] = g_s2[col0 + tid];

        float acc[2][8][4];
        #pragma unroll
        for (int mt = 0; mt < 2; mt++)
            #pragma unroll
            for (int nt = 0; nt < 8; nt++)
                #pragma unroll
                for (int k = 0; k < 4; k++) acc[mt][nt][k] = 0.0f;

        // ---- prefetch chunk 0
        {
            #pragma unroll
            for (int i = 0; i < 2; i++) {
                int idx = tid + i * 256;          // 0..511
                int r = idx >> 2, q = idx & 3;
                uint32_t dA = sbA[0] + sw(r * 64 + q * 16);
                const char* srcA = (const char*)g_Xp +
                    (((size_t)(brow0 + r) * KP + 0 * KT + q * 8) << 1);
                CP_ASYNC16(dA, srcA);
                uint32_t dB = sbB[0] + sw(r * 64 + q * 16);
                const char* srcB = (const char*)g_Sp +
                    (((size_t)(col0 + r) * KP + 0 * KT + q * 8) << 1);
                CP_ASYNC16(dB, srcB);
            }
            CP_COMMIT();
        }

        for (int c = 0; c < NCH; c++) {
            const int buf = c & 1;
            if (c + 1 < NCH) {
                const int nb = (c + 1) & 1;
                #pragma unroll
                for (int i = 0; i < 2; i++) {
                    int idx = tid + i * 256;
                    int r = idx >> 2, q = idx & 3;
                    uint32_t dA = sbA[nb] + sw(r * 64 + q * 16);
                    const char* srcA = (const char*)g_Xp +
                        (((size_t)(brow0 + r) * KP + (c + 1) * KT + q * 8) << 1);
                    CP_ASYNC16(dA, srcA);
                    uint32_t dB = sbB[nb] + sw(r * 64 + q * 16);
                    const char* srcB = (const char*)g_Sp +
                        (((size_t)(col0 + r) * KP + (c + 1) * KT + q * 8) << 1);
                    CP_ASYNC16(dB, srcB);
                }
                CP_COMMIT();
                CP_WAIT1();
            } else {
                CP_WAIT0();
            }
            __syncthreads();

            // ---- compute on buf
            #pragma unroll
            for (int ks = 0; ks < 2; ks++) {
                uint32_t a[2][4];
                #pragma unroll
                for (int mt = 0; mt < 2; mt++) {
                    uint32_t addr = sbA[buf] +
                        sw((wm * 32 + mt * 16 + lrow) * 64 + (ks * 16 + lkof) * 2);
                    LDSM_X4(a[mt][0], a[mt][1], a[mt][2], a[mt][3], addr);
                }
                #pragma unroll
                for (int ntp = 0; ntp < 4; ntp++) {
                    uint32_t b0, b1, b2, b3;
                    uint32_t addr = sbB[buf] +
                        sw((wn * 64 + ntp * 16 + lrow) * 64 + (ks * 16 + lkof) * 2);
                    LDSM_X4(b0, b1, b2, b3, addr);
                    // nt_lo = ntp*2 uses {b0,b2}; nt_hi = ntp*2+1 uses {b1,b3}
                    #pragma unroll
                    for (int mt = 0; mt < 2; mt++) {
                        MMA16816(acc[mt][ntp*2][0], acc[mt][ntp*2][1],
                                 acc[mt][ntp*2][2], acc[mt][ntp*2][3],
                                 a[mt][0], a[mt][1], a[mt][2], a[mt][3], b0, b2);
                        MMA16816(acc[mt][ntp*2+1][0], acc[mt][ntp*2+1][1],
                                 acc[mt][ntp*2+1][2], acc[mt][ntp*2+1][3],
                                 a[mt][0], a[mt][1], a[mt][2], a[mt][3], b1, b3);
                    }
                }
            }
            __syncthreads();
        }

        // ---- epilogue: score = ||s||^2 - 2*dot, running lexicographic min
        #pragma unroll
        for (int mt = 0; mt < 2; mt++)
            #pragma unroll
            for (int nt = 0; nt < 8; nt++)
                #pragma unroll
                for (int k = 0; k < 4; k++) {
                    int col_l = wn * 64 + nt * 8 + (lane & 3) * 2 + (k & 1);
                    float sc = fmaf(-2.0f, acc[mt][nt][k], s2s[col_l]);
                    int b = mt * 2 + (k >> 1);
                    int gidx = col0 + col_l;
                    if (sc < bestv[b] || (sc == bestv[b] && gidx < besti[b])) {
                        bestv[b] = sc; besti[b] = gidx;
                    }
                }
        __syncthreads();   // all done with s2s before next tile rewrites it
    }

    // ---- quad (n) reduce within warp, then cross-wn via smem
    #pragma unroll
    for (int b = 0; b < 4; b++) {
        #pragma unroll
        for (int o = 1; o <= 2; o <<= 1) {
            float ov = __shfl_xor_sync(0xffffffffu, bestv[b], o);
            int   oi = __shfl_xor_sync(0xffffffffu, besti[b], o);
            if (ov < bestv[b] || (ov == bestv[b] && oi < besti[b])) {
                bestv[b] = ov; besti[b] = oi;
            }
        }
        if ((lane & 3) == 0) {
            int row_l = wm * 32 + (b >> 1) * 16 + (b & 1) * 8 + (lane >> 2);
            redv[wn][row_l] = bestv[b];
            redi[wn][row_l] = besti[b];
        }
    }
    __syncthreads();
    if (tid < MT) {
        float v0 = redv[0][tid], v1 = redv[1][tid];
        int   i0 = redi[0][tid], i1 = redi[1][tid];
        bool pick1 = (v1 < v0) || (v1 == v0 && i1 < i0);
        g_pval[(size_t)(brow0 + tid) * NSPLIT + grp] = pick1 ? v1 : v0;
        g_pidx[(size_t)(brow0 + tid) * NSPLIT + grp] = pick1 ? i1 : i0;
    }
}

// ---------------- final reduce + one-hot (float32 out) ----------------------
__global__ void final_kernel(const void* __restrict__ labs, float* __restrict__ out) {
    int b = blockIdx.x;
    int lane = threadIdx.x;
    float bv = 3.4e38f;
    int   bi = NS + 1;
    if (lane < NSPLIT) {
        bv = g_pval[(size_t)b * NSPLIT + lane];
        bi = g_pidx[(size_t)b * NSPLIT + lane];
    }
    #pragma unroll
    for (int o = 16; o; o >>= 1) {
        float ov = __shfl_xor_sync(0xffffffffu, bv, o);
        int   oi = __shfl_xor_sync(0xffffffffu, bi, o);
        if (ov < bv || (ov == bv && oi < bi)) { bv = ov; bi = oi; }
    }
    bi = min(max(bi, 0), NS - 1);
    int label;
    if (g_lab64) label = (int)((const long long*)labs)[bi];
    else         label = ((const int*)labs)[bi];

    for (int c = lane; c < NC; c += 32)
        out[(size_t)b * NC + c] = (c == label) ? 1.0f : 0.0f;
}

// ---------------- launch -----------------------------------------------------
extern "C" void kernel_launch(void* const* d_in, const int* in_sizes, int n_in,
                              void* d_out, int out_size) {
    const float* X = 0;
    const float* S = 0;
    const void*  L = 0;
    for (int i = 0; i < n_in; i++) {
        if (in_sizes[i] == BQ * DD)      X = (const float*)d_in[i];
        else if (in_sizes[i] == NS * DD) S = (const float*)d_in[i];
        else if (in_sizes[i] == NS)      L = d_in[i];
    }
    float* out = (float*)d_out;

    detect_labels_kernel<<<1, 32>>>((const int*)L);
    s2_kernel<<<NS / 8, dim3(32, 8)>>>(S);
    pack_kernel<<<(BQ * DD + 255) / 256, 256>>>(X, BQ, 0);
    pack_kernel<<<(NS * DD + 255) / 256, 256>>>(S, NS, 1);
    knn_mma_kernel<<<dim3(BQ / MT, NSPLIT), 256>>>();
    final_kernel<<<BQ, 32>>>(L, out);
}

// round 10
// speedup vs baseline: 2.4039x; 1.2920x over previous
#include <cuda_runtime.h>
#include <cuda_bf16.h>
#include <cstdint>

#define BQ 2048
#define NS 32768
#define DD 256
#define NC 100

#define MT 128              // CTA M tile
#define NT 128              // CTA N tile
#define KT 32               // bf16 per K chunk
#define NCH (DD / KT)       // 8 chunks (K = 256, hi-only)
#define NSPLIT 18
#define NTILES (NS / NT)    // 256
#define MARGIN 8.0f

// ---------------- device globals (no runtime allocation allowed) -----------
__device__ __nv_bfloat16 g_Xh[(size_t)BQ * DD];   // 1 MB
__device__ __nv_bfloat16 g_Sh[(size_t)NS * DD];   // 16 MB
__device__ float g_sc[(size_t)BQ * NS];           // 268 MB approx scores
__device__ float g_s2[NS];
__device__ float g_pval[BQ * NSPLIT];
__device__ int   g_pidx[BQ * NSPLIT];
__device__ int   g_lab64;

// ---------------- helpers ---------------------------------------------------
__device__ __forceinline__ uint32_t smem_u32(const void* p) {
    uint32_t a;
    asm("{ .reg .u64 t; cvta.to.shared.u64 t, %1; cvt.u32.u64 %0, t; }"
        : "=r"(a) : "l"(p));
    return a;
}
__device__ __forceinline__ uint32_t sw(uint32_t byte_off) {
    return byte_off ^ ((byte_off >> 3) & 0x30);
}

#define CP_ASYNC16(dst, src) \
    asm volatile("cp.async.cg.shared.global [%0], [%1], 16;" :: "r"(dst), "l"(src) : "memory")
#define CP_COMMIT() asm volatile("cp.async.commit_group;" ::: "memory")
#define CP_WAIT1()  asm volatile("cp.async.wait_group 1;" ::: "memory")
#define CP_WAIT0()  asm volatile("cp.async.wait_group 0;" ::: "memory")

#define LDSM_X4(r0, r1, r2, r3, addr) \
    asm volatile("ldmatrix.sync.aligned.m8n8.x4.shared.b16 {%0,%1,%2,%3}, [%4];" \
                 : "=r"(r0), "=r"(r1), "=r"(r2), "=r"(r3) : "r"(addr))

#define MMA16816(c0, c1, c2, c3, a0, a1, a2, a3, b0, b1) \
    asm volatile("mma.sync.aligned.m16n8k16.row.col.f32.bf16.bf16.f32 " \
                 "{%0,%1,%2,%3}, {%4,%5,%6,%7}, {%8,%9}, {%0,%1,%2,%3};" \
                 : "+f"(c0), "+f"(c1), "+f"(c2), "+f"(c3) \
                 : "r"(a0), "r"(a1), "r"(a2), "r"(a3), "r"(b0), "r"(b1))

// ---------------- small kernels ---------------------------------------------
__global__ void detect_labels_kernel(const int* __restrict__ labs) {
    if (threadIdx.x == 0) {
        int f = 1;
        for (int i = 0; i < 128; i++)
            if (labs[2 * i + 1] != 0) { f = 0; break; }
        g_lab64 = f;
    }
}

__global__ void s2_kernel(const float* __restrict__ S) {
    int row = blockIdx.x * 8 + threadIdx.y;
    const float4* p = (const float4*)(S + (size_t)row * DD);
    float s = 0.0f;
    #pragma unroll
    for (int i = threadIdx.x; i < DD / 4; i += 32) {
        float4 v = p[i];
        s += v.x * v.x + v.y * v.y + v.z * v.z + v.w * v.w;
    }
    #pragma unroll
    for (int o = 16; o; o >>= 1) s += __shfl_xor_sync(0xffffffffu, s, o);
    if (threadIdx.x == 0) g_s2[row] = s;
}

// f32 -> bf16; destination selected IN DEVICE CODE (never pass __device__
// symbols as host-side kernel arguments — host sees the shadow symbol).
__global__ void pack_kernel(const float* __restrict__ src, int total, int isS) {
    int idx = blockIdx.x * 256 + threadIdx.x;
    if (idx < total) {
        __nv_bfloat16 v = __float2bfloat16(src[idx]);
        if (isS) g_Sh[idx] = v;
        else     g_Xh[idx] = v;
    }
}

// ---------------- pass 1: bf16 GEMM + score store + partial argmin ----------
// grid (BQ/MT, NSPLIT) = (16, 18), block 256 (8 warps: 4 m x 2 n)
__global__ void __launch_bounds__(256)
knn_mma_kernel() {
    __shared__ __align__(128) char As[2][MT * KT * 2];
    __shared__ __align__(128) char Bs[2][NT * KT * 2];
    __shared__ float s2s[NT];
    __shared__ float redv[2][MT];
    __shared__ int   redi[2][MT];

    const int tid  = threadIdx.x;
    const int lane = tid & 31;
    const int wid  = tid >> 5;
    const int wm   = wid & 3;
    const int wn   = wid >> 2;
    const int brow0 = blockIdx.x * MT;
    const int grp   = blockIdx.y;

    const uint32_t sbA[2] = { smem_u32(As[0]), smem_u32(As[1]) };
    const uint32_t sbB[2] = { smem_u32(Bs[0]), smem_u32(Bs[1]) };

    float bestv[4];
    int   besti[4];
    #pragma unroll
    for (int b = 0; b < 4; b++) { bestv[b] = 3.4e38f; besti[b] = 0; }

    const int lrow = lane & 15;
    const int lkof = (lane >> 4) * 8;

    for (int st = grp; st < NTILES; st += NSPLIT) {
        const int col0 = st * NT;
        if (tid < NT) s2s[tid] = g_s2[col0 + tid];

        float acc[2][8][4];
        #pragma unroll
        for (int mt = 0; mt < 2; mt++)
            #pragma unroll
            for (int nt = 0; nt < 8; nt++)
                #pragma unroll
                for (int k = 0; k < 4; k++) acc[mt][nt][k] = 0.0f;

        {   // prefetch chunk 0
            #pragma unroll
            for (int i = 0; i < 2; i++) {
                int idx = tid + i * 256;
                int r = idx >> 2, q = idx & 3;
                CP_ASYNC16(sbA[0] + sw(r * 64 + q * 16),
                           (const char*)g_Xh + (((size_t)(brow0 + r) * DD + q * 8) << 1));
                CP_ASYNC16(sbB[0] + sw(r * 64 + q * 16),
                           (const char*)g_Sh + (((size_t)(col0 + r) * DD + q * 8) << 1));
            }
            CP_COMMIT();
        }

        for (int c = 0; c < NCH; c++) {
            const int buf = c & 1;
            if (c + 1 < NCH) {
                const int nb = (c + 1) & 1;
                #pragma unroll
                for (int i = 0; i < 2; i++) {
                    int idx = tid + i * 256;
                    int r = idx >> 2, q = idx & 3;
                    CP_ASYNC16(sbA[nb] + sw(r * 64 + q * 16),
                               (const char*)g_Xh + (((size_t)(brow0 + r) * DD + (c + 1) * KT + q * 8) << 1));
                    CP_ASYNC16(sbB[nb] + sw(r * 64 + q * 16),
                               (const char*)g_Sh + (((size_t)(col0 + r) * DD + (c + 1) * KT + q * 8) << 1));
                }
                CP_COMMIT();
                CP_WAIT1();
            } else {
                CP_WAIT0();
            }
            __syncthreads();

            #pragma unroll
            for (int ks = 0; ks < 2; ks++) {
                uint32_t a[2][4];
                #pragma unroll
                for (int mt = 0; mt < 2; mt++) {
                    uint32_t addr = sbA[buf] +
                        sw((wm * 32 + mt * 16 + lrow) * 64 + (ks * 16 + lkof) * 2);
                    LDSM_X4(a[mt][0], a[mt][1], a[mt][2], a[mt][3], addr);
                }
                #pragma unroll
                for (int ntp = 0; ntp < 4; ntp++) {
                    uint32_t b0, b1, b2, b3;
                    uint32_t addr = sbB[buf] +
                        sw((wn * 64 + ntp * 16 + lrow) * 64 + (ks * 16 + lkof) * 2);
                    LDSM_X4(b0, b1, b2, b3, addr);
                    #pragma unroll
                    for (int mt = 0; mt < 2; mt++) {
                        MMA16816(acc[mt][ntp*2][0], acc[mt][ntp*2][1],
                                 acc[mt][ntp*2][2], acc[mt][ntp*2][3],
                                 a[mt][0], a[mt][1], a[mt][2], a[mt][3], b0, b2);
                        MMA16816(acc[mt][ntp*2+1][0], acc[mt][ntp*2+1][1],
                                 acc[mt][ntp*2+1][2], acc[mt][ntp*2+1][3],
                                 a[mt][0], a[mt][1], a[mt][2], a[mt][3], b1, b3);
                    }
                }
            }
            __syncthreads();
        }

        // epilogue: sc = s2 - 2*dot; store to g_sc; running lexicographic min
        #pragma unroll
        for (int mt = 0; mt < 2; mt++)
            #pragma unroll
            for (int nt = 0; nt < 8; nt++)
                #pragma unroll
                for (int kp = 0; kp < 2; kp++) {
                    int row_l = wm * 32 + mt * 16 + kp * 8 + (lane >> 2);
                    int col_l = wn * 64 + nt * 8 + (lane & 3) * 2;
                    float sc0 = fmaf(-2.0f, acc[mt][nt][kp*2+0], s2s[col_l]);
                    float sc1 = fmaf(-2.0f, acc[mt][nt][kp*2+1], s2s[col_l + 1]);
                    *(float2*)&g_sc[(size_t)(brow0 + row_l) * NS + col0 + col_l] =
                        make_float2(sc0, sc1);
                    int b = mt * 2 + kp;
                    if (sc0 < bestv[b] || (sc0 == bestv[b] && col0 + col_l < besti[b])) {
                        bestv[b] = sc0; besti[b] = col0 + col_l;
                    }
                    if (sc1 < bestv[b] || (sc1 == bestv[b] && col0 + col_l + 1 < besti[b])) {
                        bestv[b] = sc1; besti[b] = col0 + col_l + 1;
                    }
                }
        __syncthreads();
    }

    // n-direction reduce within warp quads, then across wn via smem
    #pragma unroll
    for (int b = 0; b < 4; b++) {
        #pragma unroll
        for (int o = 1; o <= 2; o <<= 1) {
            float ov = __shfl_xor_sync(0xffffffffu, bestv[b], o);
            int   oi = __shfl_xor_sync(0xffffffffu, besti[b], o);
            if (ov < bestv[b] || (ov == bestv[b] && oi < besti[b])) {
                bestv[b] = ov; besti[b] = oi;
            }
        }
        if ((lane & 3) == 0) {
            int row_l = wm * 32 + (b >> 1) * 16 + (b & 1) * 8 + (lane >> 2);
            redv[wn][row_l] = bestv[b];
            redi[wn][row_l] = besti[b];
        }
    }
    __syncthreads();
    if (tid < MT) {
        float v0 = redv[0][tid], v1 = redv[1][tid];
        int   i0 = redi[0][tid], i1 = redi[1][tid];
        bool pick1 = (v1 < v0) || (v1 == v0 && i1 < i0);
        g_pval[(size_t)(brow0 + tid) * NSPLIT + blockIdx.y] = pick1 ? v1 : v0;
        g_pidx[(size_t)(brow0 + tid) * NSPLIT + blockIdx.y] = pick1 ? i1 : i0;
    }
}

// ---------------- pass 2: candidate rescore (exact fp32) + one-hot ----------
// grid = BQ, block = 256
__global__ void __launch_bounds__(256)
rescore_kernel(const float* __restrict__ X, const float* __restrict__ S,
               const void* __restrict__ labs, float* __restrict__ out) {
    __shared__ float xq[DD];
    __shared__ float wv[8];
    __shared__ int   wi[8];
    __shared__ int   s_label;

    const int q = blockIdx.x;
    const int tid = threadIdx.x;
    const int lane = tid & 31;
    const int wid = tid >> 5;

    xq[tid] = X[(size_t)q * DD + tid];   // 256 threads, 256 dims

    // approx min over NSPLIT partials (warp 0)
    float am = 3.4e38f;
    if (tid < NSPLIT) am = g_pval[(size_t)q * NSPLIT + tid];
    if (wid == 0) {
        #pragma unroll
        for (int o = 16; o; o >>= 1)
            am = fminf(am, __shfl_xor_sync(0xffffffffu, am, o));
        if (lane == 0) wv[0] = am;
    }
    __syncthreads();
    const float cutoff = wv[0] + MARGIN;
    __syncthreads();

    // scan this query's approx scores; exact-rescore candidates
    float bv = 3.4e38f;
    int   bi = NS + 1;
    const float* scrow = &g_sc[(size_t)q * NS];
    for (int n = tid; n < NS; n += 256) {
        float sa = scrow[n];
        if (sa <= cutoff) {
            const float* srow = S + (size_t)n * DD;
            float dot = 0.0f;
            #pragma unroll 8
            for (int k = 0; k < DD; k++) dot = fmaf(xq[k], srow[k], dot);
            float sc = fmaf(-2.0f, dot, g_s2[n]);
            if (sc < bv || (sc == bv && n < bi)) { bv = sc; bi = n; }
        }
    }
    // block lexicographic min reduce
    #pragma unroll
    for (int o = 16; o; o >>= 1) {
        float ov = __shfl_xor_sync(0xffffffffu, bv, o);
        int   oi = __shfl_xor_sync(0xffffffffu, bi, o);
        if (ov < bv || (ov == bv && oi < bi)) { bv = ov; bi = oi; }
    }
    if (lane == 0) { wv[wid] = bv; wi[wid] = bi; }
    __syncthreads();
    if (tid == 0) {
        float fbv = wv[0]; int fbi = wi[0];
        #pragma unroll
        for (int w = 1; w < 8; w++) {
            if (wv[w] < fbv || (wv[w] == fbv && wi[w] < fbi)) { fbv = wv[w]; fbi = wi[w]; }
        }
        fbi = min(max(fbi, 0), NS - 1);
        int label;
        if (g_lab64) label = (int)((const long long*)labs)[fbi];
        else         label = ((const int*)labs)[fbi];
        s_label = label;
    }
    __syncthreads();
    if (tid < NC) out[(size_t)q * NC + tid] = (tid == s_label) ? 1.0f : 0.0f;
}

// ---------------- launch -----------------------------------------------------
extern "C" void kernel_launch(void* const* d_in, const int* in_sizes, int n_in,
                              void* d_out, int out_size) {
    const float* X = 0;
    const float* S = 0;
    const void*  L = 0;
    for (int i = 0; i < n_in; i++) {
        if (in_sizes[i] == BQ * DD)      X = (const float*)d_in[i];
        else if (in_sizes[i] == NS * DD) S = (const float*)d_in[i];
        else if (in_sizes[i] == NS)      L = d_in[i];
    }
    float* out = (float*)d_out;

    detect_labels_kernel<<<1, 32>>>((const int*)L);
    s2_kernel<<<NS / 8, dim3(32, 8)>>>(S);
    pack_kernel<<<(BQ * DD + 255) / 256, 256>>>(X, BQ * DD, 0);
    pack_kernel<<<(NS * DD + 255) / 256, 256>>>(S, NS * DD, 1);
    knn_mma_kernel<<<dim3(BQ / MT, NSPLIT), 256>>>();
    rescore_kernel<<<BQ, 256>>>(X, S, L, out);
}